// round 6
// baseline (speedup 1.0000x reference)
#include <cuda_runtime.h>
#include <cuda_bf16.h>
#include <cstdint>

// Problem dims
#define BATCH 1024
#define TSTEPS 200
#define DDIM 128

#define NBLK 128          // 16 m-groups x 8 cell-CTAs, 1 CTA/SM
#define THREADS 256
#define MT 64             // batch rows per CTA
#define NGRP 16
#define GRP_CTAS 8
#define CT_CELLS 16       // cells per CTA -> 64 gate-columns

// SMEM (bytes): A1 (layer1), A2 (layer2), B shared. [rows x 512B] swizzled bf16.
#define SM_A1HI 0
#define SM_A1LO 32768
#define SM_A2HI 65536
#define SM_A2LO 98304
#define SM_BHI  131072
#define SM_BLO  163840
#define SMEM_BYTES 196608

// Persistent globals (no allocation allowed)
__device__ __nv_bfloat16 gx_hi[BATCH*TSTEPS*DDIM];
__device__ __nv_bfloat16 gx_lo[BATCH*TSTEPS*DDIM];
__device__ __nv_bfloat16 gh1_hi[2][BATCH*DDIM];
__device__ __nv_bfloat16 gh1_lo[2][BATCH*DDIM];
__device__ __nv_bfloat16 gh2_hi[2][BATCH*DDIM];
__device__ __nv_bfloat16 gh2_lo[2][BATCH*DDIM];
__device__ unsigned g0_cnt[NGRP], g0_gen[NGRP];
__device__ unsigned g1_cnt[NGRP], g1_gen[NGRP];
__device__ unsigned g2_cnt[NGRP], g2_gen[NGRP];

// ---------------- helpers ----------------
__device__ __forceinline__ uint32_t smem_u32(const void* p){
    uint32_t a;
    asm("{ .reg .u64 t; cvta.to.shared.u64 t, %1; cvt.u32.u64 %0, t; }" : "=r"(a) : "l"(p));
    return a;
}
__device__ __forceinline__ void cpa16(uint32_t dst, const void* src){
    asm volatile("cp.async.cg.shared.global [%0], [%1], 16;" :: "r"(dst), "l"(src));
}
__device__ __forceinline__ void cp_commit(){ asm volatile("cp.async.commit_group;" ::: "memory"); }
template<int N> __device__ __forceinline__ void cp_wait(){ asm volatile("cp.async.wait_group %0;" :: "n"(N) : "memory"); }
__device__ __forceinline__ void barn(int id){ asm volatile("bar.sync %0, 128;" :: "r"(id) : "memory"); }

__device__ __forceinline__ void ldsm4(uint32_t& r0, uint32_t& r1, uint32_t& r2, uint32_t& r3, uint32_t addr){
    asm volatile("ldmatrix.sync.aligned.m8n8.x4.shared.b16 {%0,%1,%2,%3}, [%4];"
                 : "=r"(r0), "=r"(r1), "=r"(r2), "=r"(r3) : "r"(addr));
}
__device__ __forceinline__ void hmma(float* c, const uint32_t* a, uint32_t b0, uint32_t b1){
    asm volatile("mma.sync.aligned.m16n8k16.row.col.f32.bf16.bf16.f32 "
                 "{%0,%1,%2,%3}, {%4,%5,%6,%7}, {%8,%9}, {%0,%1,%2,%3};"
                 : "+f"(c[0]), "+f"(c[1]), "+f"(c[2]), "+f"(c[3])
                 : "r"(a[0]), "r"(a[1]), "r"(a[2]), "r"(a[3]), "r"(b0), "r"(b1));
}
__device__ __forceinline__ float fsig(float x){ return __fdividef(1.f, 1.f + __expf(-x)); }
__device__ __forceinline__ float ftanh_(float x){
    x = fminf(15.f, fmaxf(-15.f, x));
    float e = __expf(2.f * x);
    return __fdividef(e - 1.f, e + 1.f);
}
__device__ __forceinline__ void split1(float v, __nv_bfloat16& hi, __nv_bfloat16& lo){
    hi = __float2bfloat16(v);
    lo = __float2bfloat16(v - __bfloat162float(hi));
}
__device__ __forceinline__ void split4(float4 v, uint2& hi, uint2& lo){
    __nv_bfloat16 hx, hy, hz, hw, lx, ly, lz, lw;
    split1(v.x, hx, lx); split1(v.y, hy, ly); split1(v.z, hz, lz); split1(v.w, hw, lw);
    __nv_bfloat162 h01; h01.x = hx; h01.y = hy;
    __nv_bfloat162 h23; h23.x = hz; h23.y = hw;
    __nv_bfloat162 l01; l01.x = lx; l01.y = ly;
    __nv_bfloat162 l23; l23.x = lz; l23.y = lw;
    hi.x = *reinterpret_cast<uint32_t*>(&h01); hi.y = *reinterpret_cast<uint32_t*>(&h23);
    lo.x = *reinterpret_cast<uint32_t*>(&l01); lo.y = *reinterpret_cast<uint32_t*>(&l23);
}

// Full-CTA init barrier across the 8-CTA group; leader resets g1/g2 counters
// so absolute-target waits are replay-safe.
__device__ __forceinline__ void init_barrier(int grp){
    __syncthreads();
    if (threadIdx.x == 0){
        __threadfence();
        unsigned my = *(volatile unsigned*)&g0_gen[grp];
        unsigned old = atomicAdd(&g0_cnt[grp], 1);
        if (old == GRP_CTAS - 1){
            g0_cnt[grp] = 0;
            g1_cnt[grp] = 0; g1_gen[grp] = 0;
            g2_cnt[grp] = 0; g2_gen[grp] = 0;
            __threadfence();
            atomicAdd(&g0_gen[grp], 1);
        } else {
            while (*(volatile unsigned*)&g0_gen[grp] == my) { }
        }
        __threadfence();
    }
    __syncthreads();
}

// arrive + wait(gen >= target) among one layer's warps across the group
__device__ __forceinline__ void layer_barrier(unsigned* cnt, unsigned* gen, int grp,
                                              unsigned target, int ltid, int barid){
    barn(barid);
    if (ltid == 0){
        __threadfence();
        unsigned old = atomicAdd(&cnt[grp], 1);
        if (old == GRP_CTAS - 1){ cnt[grp] = 0; __threadfence(); atomicAdd(&gen[grp], 1); }
        while (*(volatile unsigned*)&gen[grp] < target) { }
        __threadfence();
    }
    barn(barid);
}
// pure wait
__device__ __forceinline__ void layer_wait(unsigned* gen, int grp, unsigned target, int ltid, int barid){
    if (ltid == 0){
        while (*(volatile unsigned*)&gen[grp] < target) { }
        __threadfence();
    }
    barn(barid);
}

// fill one K-half (hi+lo) of an A buffer via cp.async, 128 threads
__device__ __forceinline__ void fill_half(uint32_t sb_hi, uint32_t sb_lo,
                                          const __nv_bfloat16* __restrict__ src_hi,
                                          const __nv_bfloat16* __restrict__ src_lo,
                                          size_t row_stride, int half, int ltid){
    #pragma unroll
    for (int i = 0; i < 16; ++i){
        int idx = ltid + i * 128;          // 0..2047
        int sel = idx >> 10;               // 0 = hi, 1 = lo
        int r = (idx >> 4) & 63;
        int u = idx & 15;
        const __nv_bfloat16* s = (sel ? src_lo : src_hi) + (size_t)r * row_stride + u * 8;
        uint32_t U = (uint32_t)((half << 4) | u);
        uint32_t dst = (sel ? sb_lo : sb_hi) + r * 512 + ((U ^ (uint32_t)(r & 7)) << 4);
        cpa16(dst, s);
    }
}

// -------- pre-kernel: split x into bf16 hi/lo --------
__global__ void __launch_bounds__(256)
split_x_kernel(const float* __restrict__ x)
{
    int i = blockIdx.x * 256 + threadIdx.x;
    float4 v = reinterpret_cast<const float4*>(x)[i];
    uint2 hi, lo; split4(v, hi, lo);
    reinterpret_cast<uint2*>(gx_hi)[i] = hi;
    reinterpret_cast<uint2*>(gx_lo)[i] = lo;
}

extern __shared__ char smem[];

__global__ void __launch_bounds__(THREADS, 1)
lstm_ws_kernel(const float* __restrict__ W,
               const float* __restrict__ U,
               const float* __restrict__ bias,
               float* __restrict__ out)
{
    const uint32_t sbase = smem_u32(smem);
    const int tid = threadIdx.x;
    const int lane = tid & 31;
    const int mt = blockIdx.x >> 3;       // m-group 0..15
    const int ct = blockIdx.x & 7;
    const int m0 = mt * MT;
    const int cell0 = ct * CT_CELLS;

    // ---- build B hi/lo once (all 256 threads): n = gate*16 + cell, [64 n][256 k]
    #pragma unroll
    for (int i = 0; i < 16; ++i){
        int tsk = tid + i * THREADS;
        int n = tsk >> 6, kq = tsk & 63, k = kq * 4;
        int gate = n >> 4, cell = n & 15;
        int col = gate * 128 + cell0 + cell;
        float4 v;
        float* vv = reinterpret_cast<float*>(&v);
        #pragma unroll
        for (int j = 0; j < 4; ++j){
            int kk = k + j;
            vv[j] = (kk < 128) ? W[kk * 512 + col] : U[(kk - 128) * 512 + col];
        }
        uint2 hi, lo; split4(v, hi, lo);
        uint32_t so = n * 512 + ((((kq >> 1) ^ (n & 7)) << 4)) + ((kq & 1) << 3);
        *reinterpret_cast<uint2*>(smem + SM_BHI + so) = hi;
        *reinterpret_cast<uint2*>(smem + SM_BLO + so) = lo;
    }

    // ---- zero initial split state (slot 0)
    for (int i = tid; i < MT * DDIM / 2; i += THREADS){
        reinterpret_cast<uint32_t*>(&gh1_hi[0][m0 * DDIM])[i] = 0u;
        reinterpret_cast<uint32_t*>(&gh1_lo[0][m0 * DDIM])[i] = 0u;
        reinterpret_cast<uint32_t*>(&gh2_hi[0][m0 * DDIM])[i] = 0u;
        reinterpret_cast<uint32_t*>(&gh2_lo[0][m0 * DDIM])[i] = 0u;
    }
    init_barrier(mt);

    // ---- per-warp fragment coordinates (m32 x n32 per warp, 4 warps per layer)
    const int lwid = (tid >> 5) & 3;
    const int wm = lwid & 1, wn = lwid >> 1;
    const int a_row0 = wm * 32 + (lane & 15);
    const int a_row1 = a_row0 + 16;
    const uint32_t a0b = a_row0 * 512, a0x = (a_row0 & 7) << 4;
    const uint32_t a1b = a_row1 * 512, a1x = (a_row1 & 7) << 4;
    const uint32_t a_lk = (lane >> 4) << 4;
    const int b01 = wn * 8 + (lane & 7) + ((lane >> 4) << 4);
    const int b23 = 32 + b01;
    const uint32_t b01b = b01 * 512, b01x = (b01 & 7) << 4;
    const uint32_t b23b = b23 * 512, b23x = (b23 & 7) << 4;
    const uint32_t b_lk = ((lane >> 3) & 1) << 4;

    // epilogue coords: per (mf, rh): row = m0 + wm*32 + mf*16 + rh*8 + (lane>>2)
    const int er = m0 + wm * 32 + (lane >> 2);
    const int cellg = cell0 + wn * 8 + (lane & 3) * 2;

    float bia[4][2];
    #pragma unroll
    for (int g = 0; g < 4; ++g){
        bia[g][0] = bias[g * 128 + cellg];
        bia[g][1] = bias[g * 128 + cellg + 1];
    }

    float acc[2][4][4];
    auto run_mma = [&](uint32_t AHI, uint32_t ALO){
        #pragma unroll
        for (int mf = 0; mf < 2; ++mf)
            #pragma unroll
            for (int g = 0; g < 4; ++g){
                acc[mf][g][0] = bia[g][0]; acc[mf][g][1] = bia[g][1];
                acc[mf][g][2] = bia[g][0]; acc[mf][g][3] = bia[g][1];
            }
        #pragma unroll 4
        for (int ks = 0; ks < 16; ++ks){
            uint32_t kb = ks * 32;
            uint32_t ahi0[4], alo0[4], ahi1[4], alo1[4], bh[8], bl[8];
            uint32_t ao = kb + a_lk;
            ldsm4(ahi0[0], ahi0[1], ahi0[2], ahi0[3], sbase + AHI + a0b + (ao ^ a0x));
            ldsm4(alo0[0], alo0[1], alo0[2], alo0[3], sbase + ALO + a0b + (ao ^ a0x));
            ldsm4(ahi1[0], ahi1[1], ahi1[2], ahi1[3], sbase + AHI + a1b + (ao ^ a1x));
            ldsm4(alo1[0], alo1[1], alo1[2], alo1[3], sbase + ALO + a1b + (ao ^ a1x));
            uint32_t bo = kb + b_lk;
            ldsm4(bh[0], bh[1], bh[2], bh[3], sbase + SM_BHI + b01b + (bo ^ b01x));
            ldsm4(bh[4], bh[5], bh[6], bh[7], sbase + SM_BHI + b23b + (bo ^ b23x));
            ldsm4(bl[0], bl[1], bl[2], bl[3], sbase + SM_BLO + b01b + (bo ^ b01x));
            ldsm4(bl[4], bl[5], bl[6], bl[7], sbase + SM_BLO + b23b + (bo ^ b23x));
            #pragma unroll
            for (int g = 0; g < 4; ++g){
                hmma(acc[0][g], ahi0, bh[g*2], bh[g*2+1]);
                hmma(acc[0][g], ahi0, bl[g*2], bl[g*2+1]);
                hmma(acc[0][g], alo0, bh[g*2], bh[g*2+1]);
                hmma(acc[1][g], ahi1, bh[g*2], bh[g*2+1]);
                hmma(acc[1][g], ahi1, bl[g*2], bl[g*2+1]);
                hmma(acc[1][g], alo1, bh[g*2], bh[g*2+1]);
            }
        }
    };

    if (tid < 128){
        // ======================= LAYER 1 =======================
        const int ltid = tid;
        float c1[2][4];
        #pragma unroll
        for (int mf = 0; mf < 2; ++mf)
            #pragma unroll
            for (int j = 0; j < 4; ++j) c1[mf][j] = 0.f;

        // prime: x(0) half0 + h1(0) half1
        fill_half(sbase + SM_A1HI, sbase + SM_A1LO,
                  gx_hi + (size_t)m0 * TSTEPS * DDIM, gx_lo + (size_t)m0 * TSTEPS * DDIM,
                  (size_t)TSTEPS * DDIM, 0, ltid);
        fill_half(sbase + SM_A1HI, sbase + SM_A1LO,
                  &gh1_hi[0][m0 * DDIM], &gh1_lo[0][m0 * DDIM], DDIM, 1, ltid);
        cp_commit();

        for (int t = 0; t < TSTEPS; ++t){
            const int ns = (t + 1) & 1;
            cp_wait<0>(); barn(1);
            run_mma(SM_A1HI, SM_A1LO);
            barn(1);                      // all layer1 warps done reading A1
            if (t + 1 < TSTEPS){          // prefetch x(t+1) into half0
                fill_half(sbase + SM_A1HI, sbase + SM_A1LO,
                          gx_hi + ((size_t)m0 * TSTEPS + (t + 1)) * DDIM,
                          gx_lo + ((size_t)m0 * TSTEPS + (t + 1)) * DDIM,
                          (size_t)TSTEPS * DDIM, 0, ltid);
                cp_commit();
            }
            // epilogue
            float h1n[2][4];
            #pragma unroll
            for (int mf = 0; mf < 2; ++mf)
                #pragma unroll
                for (int j = 0; j < 4; ++j){
                    float cn = fsig(acc[mf][1][j]) * c1[mf][j]
                             + fsig(acc[mf][0][j]) * ftanh_(acc[mf][2][j]);
                    c1[mf][j] = cn;
                    h1n[mf][j] = fsig(acc[mf][3][j]) * ftanh_(cn);
                }
            if (t >= 2) layer_wait(g2_gen, mt, (unsigned)(t - 1), ltid, 1);  // backpressure
            #pragma unroll
            for (int mf = 0; mf < 2; ++mf)
                #pragma unroll
                for (int rh = 0; rh < 2; ++rh){
                    int r = er + mf * 16 + rh * 8;
                    __nv_bfloat162 hh, ll;
                    split1(h1n[mf][rh * 2 + 0], hh.x, ll.x);
                    split1(h1n[mf][rh * 2 + 1], hh.y, ll.y);
                    *reinterpret_cast<__nv_bfloat162*>(&gh1_hi[ns][r * DDIM + cellg]) = hh;
                    *reinterpret_cast<__nv_bfloat162*>(&gh1_lo[ns][r * DDIM + cellg]) = ll;
                }
            layer_barrier(g1_cnt, g1_gen, mt, (unsigned)(t + 1), ltid, 1);   // publish h1(t+1)
            // fill h1(t+1) half for own next step
            fill_half(sbase + SM_A1HI, sbase + SM_A1LO,
                      &gh1_hi[ns][m0 * DDIM], &gh1_lo[ns][m0 * DDIM], DDIM, 1, ltid);
            cp_commit();
        }
    } else {
        // ======================= LAYER 2 =======================
        const int ltid = tid - 128;
        float c2[2][4];
        #pragma unroll
        for (int mf = 0; mf < 2; ++mf)
            #pragma unroll
            for (int j = 0; j < 4; ++j) c2[mf][j] = 0.f;

        for (int t = 0; t < TSTEPS; ++t){
            const int s = t & 1, ns = s ^ 1;
            // h2(t) half (ready: own group finished step t-1)
            fill_half(sbase + SM_A2HI, sbase + SM_A2LO,
                      &gh2_hi[s][m0 * DDIM], &gh2_lo[s][m0 * DDIM], DDIM, 1, ltid);
            cp_commit();
            layer_wait(g1_gen, mt, (unsigned)(t + 1), ltid, 2);   // h1(t+1) published
            // residual loads (own cells, written by same-CTA layer1 warps)
            __nv_bfloat162 rhi[2][2], rlo[2][2];
            #pragma unroll
            for (int mf = 0; mf < 2; ++mf)
                #pragma unroll
                for (int rh = 0; rh < 2; ++rh){
                    int r = er + mf * 16 + rh * 8;
                    rhi[mf][rh] = *reinterpret_cast<const __nv_bfloat162*>(&gh1_hi[ns][r * DDIM + cellg]);
                    rlo[mf][rh] = *reinterpret_cast<const __nv_bfloat162*>(&gh1_lo[ns][r * DDIM + cellg]);
                }
            fill_half(sbase + SM_A2HI, sbase + SM_A2LO,
                      &gh1_hi[ns][m0 * DDIM], &gh1_lo[ns][m0 * DDIM], DDIM, 0, ltid);
            cp_commit();
            cp_wait<0>(); barn(2);
            run_mma(SM_A2HI, SM_A2LO);
            // epilogue + residual
            #pragma unroll
            for (int mf = 0; mf < 2; ++mf)
                #pragma unroll
                for (int rh = 0; rh < 2; ++rh){
                    int r = er + mf * 16 + rh * 8;
                    float res0 = __bfloat162float(rhi[mf][rh].x) + __bfloat162float(rlo[mf][rh].x);
                    float res1 = __bfloat162float(rhi[mf][rh].y) + __bfloat162float(rlo[mf][rh].y);
                    int j0 = rh * 2, j1 = rh * 2 + 1;
                    float cn0 = fsig(acc[mf][1][j0]) * c2[mf][j0]
                              + fsig(acc[mf][0][j0]) * ftanh_(acc[mf][2][j0]);
                    float cn1 = fsig(acc[mf][1][j1]) * c2[mf][j1]
                              + fsig(acc[mf][0][j1]) * ftanh_(acc[mf][2][j1]);
                    c2[mf][j0] = cn0; c2[mf][j1] = cn1;
                    float hv0 = fsig(acc[mf][3][j0]) * ftanh_(cn0) + res0;
                    float hv1 = fsig(acc[mf][3][j1]) * ftanh_(cn1) + res1;
                    __nv_bfloat162 hh, ll;
                    split1(hv0, hh.x, ll.x);
                    split1(hv1, hh.y, ll.y);
                    *reinterpret_cast<__nv_bfloat162*>(&gh2_hi[ns][r * DDIM + cellg]) = hh;
                    *reinterpret_cast<__nv_bfloat162*>(&gh2_lo[ns][r * DDIM + cellg]) = ll;
                    float2 ov; ov.x = hv0; ov.y = hv1;
                    *reinterpret_cast<float2*>(&out[((size_t)r * TSTEPS + t) * DDIM + cellg]) = ov;
                }
            layer_barrier(g2_cnt, g2_gen, mt, (unsigned)(t + 1), ltid, 2);
        }
    }
}

extern "C" void kernel_launch(void* const* d_in, const int* in_sizes, int n_in,
                              void* d_out, int out_size)
{
    const float* x    = (const float*)d_in[0];
    const float* W    = (const float*)d_in[1];
    const float* U    = (const float*)d_in[2];
    const float* bias = (const float*)d_in[3];
    // d_in[4] = seq_len: reference ignores it
    float* out = (float*)d_out;

    split_x_kernel<<<(BATCH * TSTEPS * DDIM / 4) / 256, 256>>>(x);

    cudaFuncSetAttribute(lstm_ws_kernel,
                         cudaFuncAttributeMaxDynamicSharedMemorySize, SMEM_BYTES);
    lstm_ws_kernel<<<NBLK, THREADS, SMEM_BYTES>>>(W, U, bias, out);
}

// round 8
// speedup vs baseline: 1.2368x; 1.2368x over previous
#include <cuda_runtime.h>
#include <cuda_bf16.h>
#include <cstdint>

// Problem dims
#define BATCH 1024
#define TSTEPS 200
#define DDIM 128

#define NBLK 128
#define THREADS 256
#define CLUSTER_SIZE 4
#define MT 32             // batch rows per cluster (all 4 CTAs share these rows)

// SMEM layout (bytes)
#define SM_BHI 0          // B hi: [128 n][512 B] = 64 KB
#define SM_BLO 65536      // B lo: 64 KB
#define SM_X   131072     // X[2 slots]: slot = hi 8 KB + lo 8 KB  (32 KB)
#define SM_H1  163840     // H1[2 slots]: hi 8 KB + lo 8 KB        (32 KB)
#define SM_H2  196608     // H2[2 slots]                            (32 KB)
#define SMEM_BYTES 229376

// x pre-split (device globals; no allocation allowed)
__device__ __nv_bfloat16 gx_hi[BATCH*TSTEPS*DDIM];
__device__ __nv_bfloat16 gx_lo[BATCH*TSTEPS*DDIM];

// ---------------- helpers ----------------
__device__ __forceinline__ uint32_t smem_u32(const void* p){
    uint32_t a;
    asm("{ .reg .u64 t; cvta.to.shared.u64 t, %1; cvt.u32.u64 %0, t; }" : "=r"(a) : "l"(p));
    return a;
}
__device__ __forceinline__ uint32_t cl_rank(){
    uint32_t r; asm("mov.u32 %0, %%cluster_ctarank;" : "=r"(r)); return r;
}
__device__ __forceinline__ void cluster_sync(){
    asm volatile("barrier.cluster.arrive.aligned;" ::: "memory");
    asm volatile("barrier.cluster.wait.aligned;" ::: "memory");
}
__device__ __forceinline__ void st_cluster_u32(uint32_t laddr, uint32_t rank, uint32_t val){
    asm volatile("{ .reg .u32 ra; mapa.shared::cluster.u32 ra, %0, %1; "
                 "st.shared::cluster.b32 [ra], %2; }"
                 :: "r"(laddr), "r"(rank), "r"(val) : "memory");
}
__device__ __forceinline__ void cpa16(uint32_t dst, const void* src){
    asm volatile("cp.async.cg.shared.global [%0], [%1], 16;" :: "r"(dst), "l"(src));
}
__device__ __forceinline__ void cp_commit(){ asm volatile("cp.async.commit_group;" ::: "memory"); }
template<int N> __device__ __forceinline__ void cp_wait(){ asm volatile("cp.async.wait_group %0;" :: "n"(N) : "memory"); }

__device__ __forceinline__ void ldsm4(uint32_t& r0, uint32_t& r1, uint32_t& r2, uint32_t& r3, uint32_t addr){
    asm volatile("ldmatrix.sync.aligned.m8n8.x4.shared.b16 {%0,%1,%2,%3}, [%4];"
                 : "=r"(r0), "=r"(r1), "=r"(r2), "=r"(r3) : "r"(addr));
}
__device__ __forceinline__ void hmma(float* c, const uint32_t* a, uint32_t b0, uint32_t b1){
    asm volatile("mma.sync.aligned.m16n8k16.row.col.f32.bf16.bf16.f32 "
                 "{%0,%1,%2,%3}, {%4,%5,%6,%7}, {%8,%9}, {%0,%1,%2,%3};"
                 : "+f"(c[0]), "+f"(c[1]), "+f"(c[2]), "+f"(c[3])
                 : "r"(a[0]), "r"(a[1]), "r"(a[2]), "r"(a[3]), "r"(b0), "r"(b1));
}
__device__ __forceinline__ float fsig(float x){ return __fdividef(1.f, 1.f + __expf(-x)); }
__device__ __forceinline__ float ftanh_(float x){
    x = fminf(15.f, fmaxf(-15.f, x));
    float e = __expf(2.f * x);
    return __fdividef(e - 1.f, e + 1.f);
}
__device__ __forceinline__ void split1(float v, __nv_bfloat16& hi, __nv_bfloat16& lo){
    hi = __float2bfloat16(v);
    lo = __float2bfloat16(v - __bfloat162float(hi));
}
__device__ __forceinline__ void split4(float4 v, uint2& hi, uint2& lo){
    __nv_bfloat16 hx, hy, hz, hw, lx, ly, lz, lw;
    split1(v.x, hx, lx); split1(v.y, hy, ly); split1(v.z, hz, lz); split1(v.w, hw, lw);
    __nv_bfloat162 h01; h01.x = hx; h01.y = hy;
    __nv_bfloat162 h23; h23.x = hz; h23.y = hw;
    __nv_bfloat162 l01; l01.x = lx; l01.y = ly;
    __nv_bfloat162 l23; l23.x = lz; l23.y = lw;
    hi.x = *reinterpret_cast<uint32_t*>(&h01); hi.y = *reinterpret_cast<uint32_t*>(&h23);
    lo.x = *reinterpret_cast<uint32_t*>(&l01); lo.y = *reinterpret_cast<uint32_t*>(&l23);
}

// -------- pre-kernel: split x into bf16 hi/lo --------
__global__ void __launch_bounds__(256)
split_x_kernel(const float* __restrict__ x)
{
    int i = blockIdx.x * 256 + threadIdx.x;
    float4 v = reinterpret_cast<const float4*>(x)[i];
    uint2 hi, lo; split4(v, hi, lo);
    reinterpret_cast<uint2*>(gx_hi)[i] = hi;
    reinterpret_cast<uint2*>(gx_lo)[i] = lo;
}

extern __shared__ char smem[];

__global__ void __launch_bounds__(THREADS, 1) __cluster_dims__(CLUSTER_SIZE, 1, 1)
lstm_cluster_kernel(const float* __restrict__ W,
                    const float* __restrict__ U,
                    const float* __restrict__ bias,
                    float* __restrict__ out)
{
    const uint32_t sbase = smem_u32(smem);
    const int tid = threadIdx.x;
    const int wid = tid >> 5, lane = tid & 31;
    const uint32_t rank = cl_rank();
    const int m0 = (blockIdx.x >> 2) * MT;      // cluster id * 32 rows

    // ---- build B hi/lo once: n = gate*32 + cell_local, rows [n][256 k] = 512 B swizzled
    #pragma unroll
    for (int i = 0; i < 32; ++i){
        int tsk = tid + i * THREADS;            // 0..8191 (128 n * 64 kq)
        int n = tsk >> 6, kq = tsk & 63, k = kq * 4;
        int gate = n >> 5, cell = n & 31;
        int col = gate * 128 + (int)rank * 32 + cell;
        float4 v;
        float* vv = reinterpret_cast<float*>(&v);
        #pragma unroll
        for (int j = 0; j < 4; ++j){
            int kk = k + j;
            vv[j] = (kk < 128) ? W[kk * 512 + col] : U[(kk - 128) * 512 + col];
        }
        uint2 hi, lo; split4(v, hi, lo);
        uint32_t so = n * 512 + ((((kq >> 1) ^ (n & 7)) << 4)) + ((kq & 1) << 3);
        *reinterpret_cast<uint2*>(smem + SM_BHI + so) = hi;
        *reinterpret_cast<uint2*>(smem + SM_BLO + so) = lo;
    }

    // ---- zero H1/H2 slot 0 (local; 16 KB each covers hi+lo)
    for (int i = tid; i < 4096; i += THREADS){
        reinterpret_cast<uint32_t*>(smem + SM_H1)[i] = 0u;
        reinterpret_cast<uint32_t*>(smem + SM_H2)[i] = 0u;
    }

    // ---- prefetch x(0), x(1) into X slots 0,1
    {
        const __nv_bfloat16* bh0 = gx_hi + ((size_t)m0 * TSTEPS + 0) * DDIM;
        const __nv_bfloat16* bl0 = gx_lo + ((size_t)m0 * TSTEPS + 0) * DDIM;
        #pragma unroll
        for (int slot = 0; slot < 2; ++slot){
            #pragma unroll
            for (int i = 0; i < 4; ++i){
                int idx = tid + i * THREADS;        // 0..1023
                int sel = idx >> 9;                 // 0 hi, 1 lo
                int r = (idx >> 4) & 31;
                int u = idx & 15;
                const __nv_bfloat16* s = (sel ? bl0 : bh0)
                    + (size_t)r * TSTEPS * DDIM + (size_t)slot * DDIM + u * 8;
                uint32_t dst = sbase + SM_X + slot * 16384 + sel * 8192
                             + r * 256 + (((u ^ (r & 7)) << 4));
                cpa16(dst, s);
            }
            cp_commit();
        }
    }
    cluster_sync();   // everyone's B/H0 initialized

    // ---- per-warp coordinates: wm = m16 half (rows), ws = 8-cell slice
    const int wm = wid & 1, ws = wid >> 1;
    const int a_row = wm * 16 + (lane & 15);
    const uint32_t a_base = a_row * 256;
    const uint32_t a_xor = (a_row & 7) << 4;
    const uint32_t a_lk = (lane >> 4) << 4;
    const int n01 = ws * 8 + (lane & 7) + ((lane >> 4) << 5);   // gates 0/1 rows
    const int n23 = n01 + 64;                                    // gates 2/3 rows
    const uint32_t b01b = n01 * 512, b01x = (n01 & 7) << 4;
    const uint32_t b23b = n23 * 512, b23x = (n23 & 7) << 4;
    const uint32_t b_lk = ((lane >> 3) & 1) << 4;

    // epilogue coords: thread owns rows {R, R+8}, global cells {gc, gc+1}
    const int R = wm * 16 + (lane >> 2);
    const int gc = (int)rank * 32 + ws * 8 + (lane & 3) * 2;
    // H-buffer byte offsets for the two rows (4-byte bf162 store)
    const uint32_t hofsR  = (uint32_t)(R * 256 + (((gc >> 3) ^ (R & 7)) << 4) + ((2 * gc) & 15));
    const uint32_t hofsR8 = (uint32_t)((R + 8) * 256 + (((gc >> 3) ^ ((R + 8) & 7)) << 4) + ((2 * gc) & 15));

    float bia[4][2];
    #pragma unroll
    for (int g = 0; g < 4; ++g){
        bia[g][0] = bias[g * 128 + gc];
        bia[g][1] = bias[g * 128 + gc + 1];
    }

    float c1[4], c2[4], h1n[4];
    #pragma unroll
    for (int j = 0; j < 4; ++j){ c1[j] = 0.f; c2[j] = 0.f; }

    float acc[4][4];

    // one K-half (128 k) of the 3-pass GEMM: A from (AHI, ALO), B rows at +BOFS bytes
    #define MMA_HALF(AHI, ALO, BOFS)                                                   \
    {                                                                                  \
        _Pragma("unroll 4")                                                            \
        for (int ks = 0; ks < 8; ++ks){                                                \
            uint32_t kbA = (uint32_t)(ks * 32) + a_lk;                                 \
            uint32_t kbB = (uint32_t)(ks * 32) + (uint32_t)(BOFS) + b_lk;              \
            uint32_t ahi[4], alo[4], bh[8], bl[8];                                     \
            ldsm4(ahi[0], ahi[1], ahi[2], ahi[3], (AHI) + a_base + (kbA ^ a_xor));     \
            ldsm4(alo[0], alo[1], alo[2], alo[3], (ALO) + a_base + (kbA ^ a_xor));     \
            ldsm4(bh[0], bh[1], bh[2], bh[3], sbase + SM_BHI + b01b + (kbB ^ b01x));   \
            ldsm4(bh[4], bh[5], bh[6], bh[7], sbase + SM_BHI + b23b + (kbB ^ b23x));   \
            ldsm4(bl[0], bl[1], bl[2], bl[3], sbase + SM_BLO + b01b + (kbB ^ b01x));   \
            ldsm4(bl[4], bl[5], bl[6], bl[7], sbase + SM_BLO + b23b + (kbB ^ b23x));   \
            _Pragma("unroll")                                                          \
            for (int g = 0; g < 4; ++g){                                               \
                hmma(acc[g], ahi, bh[g*2], bh[g*2+1]);                                 \
                hmma(acc[g], ahi, bl[g*2], bl[g*2+1]);                                 \
                hmma(acc[g], alo, bh[g*2], bh[g*2+1]);                                 \
            }                                                                          \
        }                                                                              \
    }

    for (int t = 0; t < TSTEPS; ++t){
        const int s = t & 1, ns = s ^ 1;
        const uint32_t Xs   = sbase + SM_X  + s  * 16384;
        const uint32_t H1s  = sbase + SM_H1 + s  * 16384;
        const uint32_t H1ns = sbase + SM_H1 + ns * 16384;
        const uint32_t H2s  = sbase + SM_H2 + s  * 16384;
        const uint32_t H2ns = sbase + SM_H2 + ns * 16384;

        // ===== Phase 1: z1 = [x_t | h1(t)] =====
        cp_wait<1>();    // x(t) resident (x(t+1) may still be in flight)
        #pragma unroll
        for (int g = 0; g < 4; ++g){
            acc[g][0] = bia[g][0]; acc[g][1] = bia[g][1];
            acc[g][2] = bia[g][0]; acc[g][3] = bia[g][1];
        }
        MMA_HALF(Xs, Xs + 8192, 0);        // k 0..127 (x)
        MMA_HALF(H1s, H1s + 8192, 256);    // k 128..255 (h1)

        #pragma unroll
        for (int j = 0; j < 4; ++j){
            float cn = fsig(acc[1][j]) * c1[j] + fsig(acc[0][j]) * ftanh_(acc[2][j]);
            c1[j] = cn;
            h1n[j] = fsig(acc[3][j]) * ftanh_(cn);
        }
        // publish h1(t+1) split into all 4 CTAs' H1[ns]
        {
            __nv_bfloat162 hh0, ll0, hh1, ll1;
            split1(h1n[0], hh0.x, ll0.x); split1(h1n[1], hh0.y, ll0.y);
            split1(h1n[2], hh1.x, ll1.x); split1(h1n[3], hh1.y, ll1.y);
            uint32_t vh0 = *reinterpret_cast<uint32_t*>(&hh0);
            uint32_t vl0 = *reinterpret_cast<uint32_t*>(&ll0);
            uint32_t vh1 = *reinterpret_cast<uint32_t*>(&hh1);
            uint32_t vl1 = *reinterpret_cast<uint32_t*>(&ll1);
            #pragma unroll
            for (uint32_t rt = 0; rt < CLUSTER_SIZE; ++rt){
                st_cluster_u32(H1ns + hofsR, rt, vh0);
                st_cluster_u32(H1ns + 8192 + hofsR, rt, vl0);
                st_cluster_u32(H1ns + hofsR8, rt, vh1);
                st_cluster_u32(H1ns + 8192 + hofsR8, rt, vl1);
            }
        }
        cluster_sync();   // S1: h1(t+1) visible everywhere

        // refill X[s] <- x(t+2) (X readers all passed S1; commit always to keep group count uniform)
        if (t + 2 < TSTEPS){
            const __nv_bfloat16* bh0 = gx_hi + ((size_t)m0 * TSTEPS + (t + 2)) * DDIM;
            const __nv_bfloat16* bl0 = gx_lo + ((size_t)m0 * TSTEPS + (t + 2)) * DDIM;
            #pragma unroll
            for (int i = 0; i < 4; ++i){
                int idx = tid + i * THREADS;
                int sel = idx >> 9;
                int r = (idx >> 4) & 31;
                int u = idx & 15;
                const __nv_bfloat16* sp = (sel ? bl0 : bh0) + (size_t)r * TSTEPS * DDIM + u * 8;
                uint32_t dst = Xs + sel * 8192 + r * 256 + (((u ^ (r & 7)) << 4));
                cpa16(dst, sp);
            }
        }
        cp_commit();

        // ===== Phase 2: z2 = [h1(t+1) | h2(t)] =====
        #pragma unroll
        for (int g = 0; g < 4; ++g){
            acc[g][0] = bia[g][0]; acc[g][1] = bia[g][1];
            acc[g][2] = bia[g][0]; acc[g][3] = bia[g][1];
        }
        MMA_HALF(H1ns, H1ns + 8192, 0);    // k 0..127 (h1(t+1))
        MMA_HALF(H2s, H2s + 8192, 256);    // k 128..255 (h2(t))

        {
            float hv[4];
            #pragma unroll
            for (int j = 0; j < 4; ++j){
                float cn = fsig(acc[1][j]) * c2[j] + fsig(acc[0][j]) * ftanh_(acc[2][j]);
                c2[j] = cn;
                hv[j] = fsig(acc[3][j]) * ftanh_(cn) + h1n[j];   // residual
            }
            __nv_bfloat162 hh0, ll0, hh1, ll1;
            split1(hv[0], hh0.x, ll0.x); split1(hv[1], hh0.y, ll0.y);
            split1(hv[2], hh1.x, ll1.x); split1(hv[3], hh1.y, ll1.y);
            uint32_t vh0 = *reinterpret_cast<uint32_t*>(&hh0);
            uint32_t vl0 = *reinterpret_cast<uint32_t*>(&ll0);
            uint32_t vh1 = *reinterpret_cast<uint32_t*>(&hh1);
            uint32_t vl1 = *reinterpret_cast<uint32_t*>(&ll1);
            #pragma unroll
            for (uint32_t rt = 0; rt < CLUSTER_SIZE; ++rt){
                st_cluster_u32(H2ns + hofsR, rt, vh0);
                st_cluster_u32(H2ns + 8192 + hofsR, rt, vl0);
                st_cluster_u32(H2ns + hofsR8, rt, vh1);
                st_cluster_u32(H2ns + 8192 + hofsR8, rt, vl1);
            }
            float2 o0, o1;
            o0.x = hv[0]; o0.y = hv[1];
            o1.x = hv[2]; o1.y = hv[3];
            *reinterpret_cast<float2*>(&out[((size_t)(m0 + R) * TSTEPS + t) * DDIM + gc]) = o0;
            *reinterpret_cast<float2*>(&out[((size_t)(m0 + R + 8) * TSTEPS + t) * DDIM + gc]) = o1;
        }
        cluster_sync();   // S2: h2(t+1) visible everywhere
    }
    #undef MMA_HALF
}

extern "C" void kernel_launch(void* const* d_in, const int* in_sizes, int n_in,
                              void* d_out, int out_size)
{
    const float* x    = (const float*)d_in[0];
    const float* W    = (const float*)d_in[1];
    const float* U    = (const float*)d_in[2];
    const float* bias = (const float*)d_in[3];
    // d_in[4] = seq_len: reference ignores it
    float* out = (float*)d_out;

    split_x_kernel<<<(BATCH * TSTEPS * DDIM / 4) / 256, 256>>>(x);

    cudaFuncSetAttribute(lstm_cluster_kernel,
                         cudaFuncAttributeMaxDynamicSharedMemorySize, SMEM_BYTES);
    lstm_cluster_kernel<<<NBLK, THREADS, SMEM_BYTES>>>(W, U, bias, out);
}

// round 9
// speedup vs baseline: 1.3338x; 1.0784x over previous
#include <cuda_runtime.h>
#include <cuda_bf16.h>
#include <cstdint>

// Problem dims
#define BATCH 1024
#define TSTEPS 200
#define DDIM 128

#define NBLK 128
#define THREADS 256
#define CLUSTER_SIZE 4
#define MT 32             // batch rows per cluster

// SMEM layout (bytes)
#define SM_BHI 0          // B hi: [128 n][512 B] = 64 KB
#define SM_BLO 65536      // B lo: 64 KB
#define SM_X   131072     // X[2 slots] x 16 KB (hi 8K + lo 8K)
#define SM_H1  163840     // H1 buf 16 KB
#define SM_H2  180224     // H2 buf 16 KB
#define SMEM_BYTES 196608

// device globals (no allocation allowed)
__device__ __nv_bfloat16 gx_hi[BATCH*TSTEPS*DDIM];
__device__ __nv_bfloat16 gx_lo[BATCH*TSTEPS*DDIM];
// h state: [slot][row*256 + plane*128 + cell]  (plane 0 = hi, 1 = lo)
__device__ __nv_bfloat16 gh1[2][BATCH*256];
__device__ __nv_bfloat16 gh2[2][BATCH*256];

// ---------------- helpers ----------------
__device__ __forceinline__ uint32_t smem_u32(const void* p){
    uint32_t a;
    asm("{ .reg .u64 t; cvta.to.shared.u64 t, %1; cvt.u32.u64 %0, t; }" : "=r"(a) : "l"(p));
    return a;
}
__device__ __forceinline__ uint32_t cl_rank(){
    uint32_t r; asm("mov.u32 %0, %%cluster_ctarank;" : "=r"(r)); return r;
}
__device__ __forceinline__ void cl_arrive(){ asm volatile("barrier.cluster.arrive.aligned;" ::: "memory"); }
__device__ __forceinline__ void cl_wait(){ asm volatile("barrier.cluster.wait.aligned;" ::: "memory"); }
__device__ __forceinline__ void cpa16(uint32_t dst, const void* src){
    asm volatile("cp.async.cg.shared.global [%0], [%1], 16;" :: "r"(dst), "l"(src));
}
__device__ __forceinline__ void cp_commit(){ asm volatile("cp.async.commit_group;" ::: "memory"); }
template<int N> __device__ __forceinline__ void cp_wait(){ asm volatile("cp.async.wait_group %0;" :: "n"(N) : "memory"); }

__device__ __forceinline__ void ldsm4(uint32_t& r0, uint32_t& r1, uint32_t& r2, uint32_t& r3, uint32_t addr){
    asm volatile("ldmatrix.sync.aligned.m8n8.x4.shared.b16 {%0,%1,%2,%3}, [%4];"
                 : "=r"(r0), "=r"(r1), "=r"(r2), "=r"(r3) : "r"(addr));
}
__device__ __forceinline__ void hmma(float* c, const uint32_t* a, uint32_t b0, uint32_t b1){
    asm volatile("mma.sync.aligned.m16n8k16.row.col.f32.bf16.bf16.f32 "
                 "{%0,%1,%2,%3}, {%4,%5,%6,%7}, {%8,%9}, {%0,%1,%2,%3};"
                 : "+f"(c[0]), "+f"(c[1]), "+f"(c[2]), "+f"(c[3])
                 : "r"(a[0]), "r"(a[1]), "r"(a[2]), "r"(a[3]), "r"(b0), "r"(b1));
}
__device__ __forceinline__ float fsig(float x){ return __fdividef(1.f, 1.f + __expf(-x)); }
__device__ __forceinline__ float ftanh_(float x){
    x = fminf(15.f, fmaxf(-15.f, x));
    float e = __expf(2.f * x);
    return __fdividef(e - 1.f, e + 1.f);
}
__device__ __forceinline__ void split1(float v, __nv_bfloat16& hi, __nv_bfloat16& lo){
    hi = __float2bfloat16(v);
    lo = __float2bfloat16(v - __bfloat162float(hi));
}
__device__ __forceinline__ void split4(float4 v, uint2& hi, uint2& lo){
    __nv_bfloat16 hx, hy, hz, hw, lx, ly, lz, lw;
    split1(v.x, hx, lx); split1(v.y, hy, ly); split1(v.z, hz, lz); split1(v.w, hw, lw);
    __nv_bfloat162 h01; h01.x = hx; h01.y = hy;
    __nv_bfloat162 h23; h23.x = hz; h23.y = hw;
    __nv_bfloat162 l01; l01.x = lx; l01.y = ly;
    __nv_bfloat162 l23; l23.x = lz; l23.y = lw;
    hi.x = *reinterpret_cast<uint32_t*>(&h01); hi.y = *reinterpret_cast<uint32_t*>(&h23);
    lo.x = *reinterpret_cast<uint32_t*>(&l01); lo.y = *reinterpret_cast<uint32_t*>(&l23);
}

// -------- pre-kernel: split x into bf16 hi/lo --------
__global__ void __launch_bounds__(256)
split_x_kernel(const float* __restrict__ x)
{
    int i = blockIdx.x * 256 + threadIdx.x;
    float4 v = reinterpret_cast<const float4*>(x)[i];
    uint2 hi, lo; split4(v, hi, lo);
    reinterpret_cast<uint2*>(gx_hi)[i] = hi;
    reinterpret_cast<uint2*>(gx_lo)[i] = lo;
}

extern __shared__ char smem[];

__global__ void __launch_bounds__(THREADS, 1) __cluster_dims__(CLUSTER_SIZE, 1, 1)
lstm_cluster2_kernel(const float* __restrict__ W,
                     const float* __restrict__ U,
                     const float* __restrict__ bias,
                     float* __restrict__ out)
{
    const uint32_t sbase = smem_u32(smem);
    const int tid = threadIdx.x;
    const int wid = tid >> 5, lane = tid & 31;
    const uint32_t rank = cl_rank();
    const int m0 = (blockIdx.x >> 2) * MT;

    // ---- B hi/lo: n = gate*32 + cell_local, [128 n][512 B] swizzled
    #pragma unroll
    for (int i = 0; i < 32; ++i){
        int tsk = tid + i * THREADS;
        int n = tsk >> 6, kq = tsk & 63, k = kq * 4;
        int gate = n >> 5, cell = n & 31;
        int col = gate * 128 + (int)rank * 32 + cell;
        float4 v;
        float* vv = reinterpret_cast<float*>(&v);
        #pragma unroll
        for (int j = 0; j < 4; ++j){
            int kk = k + j;
            vv[j] = (kk < 128) ? W[kk * 512 + col] : U[(kk - 128) * 512 + col];
        }
        uint2 hi, lo; split4(v, hi, lo);
        uint32_t so = n * 512 + ((((kq >> 1) ^ (n & 7)) << 4)) + ((kq & 1) << 3);
        *reinterpret_cast<uint2*>(smem + SM_BHI + so) = hi;
        *reinterpret_cast<uint2*>(smem + SM_BLO + so) = lo;
    }

    // ---- per-warp coordinates
    const int wm = wid & 1, ws = wid >> 1;
    const int a_row = wm * 16 + (lane & 15);
    const uint32_t a_base = a_row * 256;
    const uint32_t a_xor = (a_row & 7) << 4;
    const uint32_t a_lk = (lane >> 4) << 4;
    const int n01 = ws * 8 + (lane & 7) + ((lane >> 4) << 5);
    const int n23 = n01 + 64;
    const uint32_t b01b = n01 * 512, b01x = (n01 & 7) << 4;
    const uint32_t b23b = n23 * 512, b23x = (n23 & 7) << 4;
    const uint32_t b_lk = ((lane >> 3) & 1) << 4;

    // epilogue coords
    const int R = wm * 16 + (lane >> 2);          // local rows R, R+8
    const int gc = (int)rank * 32 + ws * 8 + (lane & 3) * 2;  // cells gc, gc+1

    // ---- zero h2(0) own slice in global (slot 0)
    {
        __nv_bfloat162 z; z.x = __float2bfloat16(0.f); z.y = z.x;
        #pragma unroll
        for (int rh = 0; rh < 2; ++rh){
            int r = m0 + R + rh * 8;
            *reinterpret_cast<__nv_bfloat162*>(&gh2[0][r * 256 + gc]) = z;
            *reinterpret_cast<__nv_bfloat162*>(&gh2[0][r * 256 + 128 + gc]) = z;
        }
    }

    // ---- prefetch x(0), x(1)
    #pragma unroll
    for (int slot = 0; slot < 2; ++slot){
        #pragma unroll
        for (int i = 0; i < 4; ++i){
            int idx = tid + i * THREADS;          // 0..1023
            int pl = idx >> 9, r = (idx >> 4) & 31, u = idx & 15;
            const __nv_bfloat16* sp = (pl ? gx_lo : gx_hi)
                + ((size_t)(m0 + r) * TSTEPS + slot) * DDIM + u * 8;
            uint32_t dst = sbase + SM_X + slot * 16384 + pl * 8192
                         + r * 256 + (((u ^ (r & 7)) << 4));
            cpa16(dst, sp);
        }
        cp_commit();
    }
    cp_wait<0>();
    __syncthreads();
    cl_arrive(); cl_wait();      // gh2 zeros visible cluster-wide

    float bia[4][2];
    #pragma unroll
    for (int g = 0; g < 4; ++g){
        bia[g][0] = bias[g * 128 + gc];
        bia[g][1] = bias[g * 128 + gc + 1];
    }

    float c1[4], c2[4], h1n[4];
    #pragma unroll
    for (int j = 0; j < 4; ++j){ c1[j] = 0.f; c2[j] = 0.f; }

    float acc1[4][4], acc2[4][4];

    #define ACC_INIT(A)                                         \
        _Pragma("unroll")                                       \
        for (int g = 0; g < 4; ++g){                            \
            A[g][0] = bia[g][0]; A[g][1] = bia[g][1];           \
            A[g][2] = bia[g][0]; A[g][3] = bia[g][1];           \
        }

    // one K-half (128 k): A from (AHI, ALO) abs smem addrs; B rows at +BOFS bytes
    #define MMA_HALF(A, AHI, ALO, BOFS)                                                \
    {                                                                                  \
        _Pragma("unroll 4")                                                            \
        for (int ks = 0; ks < 8; ++ks){                                                \
            uint32_t kbA = (uint32_t)(ks * 32) + a_lk;                                 \
            uint32_t kbB = (uint32_t)(ks * 32) + (uint32_t)(BOFS) + b_lk;              \
            uint32_t ahi[4], alo[4], bh[8], bl[8];                                     \
            ldsm4(ahi[0], ahi[1], ahi[2], ahi[3], (AHI) + a_base + (kbA ^ a_xor));     \
            ldsm4(alo[0], alo[1], alo[2], alo[3], (ALO) + a_base + (kbA ^ a_xor));     \
            ldsm4(bh[0], bh[1], bh[2], bh[3], sbase + SM_BHI + b01b + (kbB ^ b01x));   \
            ldsm4(bh[4], bh[5], bh[6], bh[7], sbase + SM_BHI + b23b + (kbB ^ b23x));   \
            ldsm4(bl[0], bl[1], bl[2], bl[3], sbase + SM_BLO + b01b + (kbB ^ b01x));   \
            ldsm4(bl[4], bl[5], bl[6], bl[7], sbase + SM_BLO + b23b + (kbB ^ b23x));   \
            _Pragma("unroll")                                                          \
            for (int g = 0; g < 4; ++g){                                               \
                hmma(A[g], ahi, bh[g*2], bh[g*2+1]);                                   \
                hmma(A[g], ahi, bl[g*2], bl[g*2+1]);                                   \
                hmma(A[g], alo, bh[g*2], bh[g*2+1]);                                   \
            }                                                                          \
        }                                                                              \
    }

    // prologue: acc1 = z1(0) = bias + x(0)·W   (h1(0)=0)
    ACC_INIT(acc1);
    MMA_HALF(acc1, sbase + SM_X, sbase + SM_X + 8192, 0);

    for (int t = 0; t < TSTEPS; ++t){
        const int s = t & 1, ns = s ^ 1;
        const uint32_t Xnext = sbase + SM_X + ns * 16384;
        const uint32_t Xcur  = sbase + SM_X + s * 16384;
        const uint32_t H1b = sbase + SM_H1, H2b = sbase + SM_H2;

        // ===== E1: h1(t+1) from acc1 =====
        #pragma unroll
        for (int j = 0; j < 4; ++j){
            float cn = fsig(acc1[1][j]) * c1[j] + fsig(acc1[0][j]) * ftanh_(acc1[2][j]);
            c1[j] = cn;
            h1n[j] = fsig(acc1[3][j]) * ftanh_(cn);
        }
        // P1: publish own h1 slice to global slot ns
        #pragma unroll
        for (int rh = 0; rh < 2; ++rh){
            int r = m0 + R + rh * 8;
            __nv_bfloat162 hh, ll;
            split1(h1n[rh * 2 + 0], hh.x, ll.x);
            split1(h1n[rh * 2 + 1], hh.y, ll.y);
            *reinterpret_cast<__nv_bfloat162*>(&gh1[ns][r * 256 + gc]) = hh;
            *reinterpret_cast<__nv_bfloat162*>(&gh1[ns][r * 256 + 128 + gc]) = ll;
        }

        if (t > 0) cl_wait();    // B_{t-1}: h2(t) stores visible; X[s]/H2buf readers done

        // Ga: H2buf <- gh2[s] (h2(t)) ; X[s] <- x(t+2)
        #pragma unroll
        for (int i = 0; i < 4; ++i){
            int idx = tid + i * THREADS;
            int pl = idx >> 9, r = (idx >> 4) & 31, u = idx & 15;
            uint32_t sw = (uint32_t)(r * 256 + (((u ^ (r & 7)) << 4)));
            cpa16(H2b + pl * 8192 + sw, &gh2[s][(m0 + r) * 256 + pl * 128 + u * 8]);
        }
        if (t + 2 < TSTEPS){
            #pragma unroll
            for (int i = 0; i < 4; ++i){
                int idx = tid + i * THREADS;
                int pl = idx >> 9, r = (idx >> 4) & 31, u = idx & 15;
                const __nv_bfloat16* sp = (pl ? gx_lo : gx_hi)
                    + ((size_t)(m0 + r) * TSTEPS + (t + 2)) * DDIM + u * 8;
                cpa16(Xcur + pl * 8192 + r * 256 + (((u ^ (r & 7)) << 4)), sp);
            }
        }
        cp_commit();

        cl_arrive();             // A_t (h1(t+1) release)

        // M1x(t+1): covers the A_t barrier skew (no cross-CTA deps)
        if (t + 1 < TSTEPS){
            cp_wait<1>();        // X[ns] long since done (only Ga pending)
            ACC_INIT(acc1);
            MMA_HALF(acc1, Xnext, Xnext + 8192, 0);
        }

        cl_wait();               // A_t: all ranks' h1(t+1) visible

        // Gb: H1buf <- gh1[ns] (h1(t+1))
        #pragma unroll
        for (int i = 0; i < 4; ++i){
            int idx = tid + i * THREADS;
            int pl = idx >> 9, r = (idx >> 4) & 31, u = idx & 15;
            uint32_t sw = (uint32_t)(r * 256 + (((u ^ (r & 7)) << 4)));
            cpa16(H1b + pl * 8192 + sw, &gh1[ns][(m0 + r) * 256 + pl * 128 + u * 8]);
        }
        cp_commit();

        cp_wait<1>();            // Ga done (mine); barrier below makes it CTA-wide
        __syncthreads();
        // M2h2: z2 += h2(t)·U   (covers Gb latency)
        ACC_INIT(acc2);
        MMA_HALF(acc2, H2b, H2b + 8192, 256);

        cp_wait<0>();            // Gb done
        __syncthreads();
        if (t + 1 < TSTEPS)
            MMA_HALF(acc1, H1b, H1b + 8192, 256);   // M1h(t+1): z1 += h1(t+1)·U
        MMA_HALF(acc2, H1b, H1b + 8192, 0);         // M2h1: z2 += h1(t+1)·W

        // ===== E2 + publish h2(t+1) + out =====
        #pragma unroll
        for (int rh = 0; rh < 2; ++rh){
            int j0 = rh * 2, j1 = rh * 2 + 1;
            float cn0 = fsig(acc2[1][j0]) * c2[j0] + fsig(acc2[0][j0]) * ftanh_(acc2[2][j0]);
            float cn1 = fsig(acc2[1][j1]) * c2[j1] + fsig(acc2[0][j1]) * ftanh_(acc2[2][j1]);
            c2[j0] = cn0; c2[j1] = cn1;
            float hv0 = fsig(acc2[3][j0]) * ftanh_(cn0) + h1n[j0];
            float hv1 = fsig(acc2[3][j1]) * ftanh_(cn1) + h1n[j1];
            int r = m0 + R + rh * 8;
            __nv_bfloat162 hh, ll;
            split1(hv0, hh.x, ll.x);
            split1(hv1, hh.y, ll.y);
            *reinterpret_cast<__nv_bfloat162*>(&gh2[ns][r * 256 + gc]) = hh;
            *reinterpret_cast<__nv_bfloat162*>(&gh2[ns][r * 256 + 128 + gc]) = ll;
            float2 ov; ov.x = hv0; ov.y = hv1;
            *reinterpret_cast<float2*>(&out[((size_t)r * TSTEPS + t) * DDIM + gc]) = ov;
        }

        cl_arrive();             // B_t (h2(t+1) release)
    }
    cl_wait();                   // consume final B arrive

    #undef MMA_HALF
    #undef ACC_INIT
}

extern "C" void kernel_launch(void* const* d_in, const int* in_sizes, int n_in,
                              void* d_out, int out_size)
{
    const float* x    = (const float*)d_in[0];
    const float* W    = (const float*)d_in[1];
    const float* U    = (const float*)d_in[2];
    const float* bias = (const float*)d_in[3];
    // d_in[4] = seq_len: reference ignores it
    float* out = (float*)d_out;

    split_x_kernel<<<(BATCH * TSTEPS * DDIM / 4) / 256, 256>>>(x);

    cudaFuncSetAttribute(lstm_cluster2_kernel,
                         cudaFuncAttributeMaxDynamicSharedMemorySize, SMEM_BYTES);
    lstm_cluster2_kernel<<<NBLK, THREADS, SMEM_BYTES>>>(W, U, bias, out);
}